// round 14
// baseline (speedup 1.0000x reference)
#include <cuda_runtime.h>
#include <cuda_bf16.h>
#include <cstdint>

#define B_    32
#define T_    512
#define H_    256
#define WDIM_ 300

typedef unsigned long long u64;

// ---------------- scratch (device globals; no allocation allowed) ----------------
__device__ __align__(16) __nv_bfloat16 g_zhi[16384 * 256];       // z split hi  [r][k]
__device__ __align__(16) __nv_bfloat16 g_zlo[16384 * 256];       // z split lo  [r][k]
__device__ __align__(16) __nv_bfloat16 g_wt[2][2][1024][256];    // [dir][part][c][k]
__device__ __align__(16) float g_gates[2 * 512 * 1024 * 32];     // [dir][t][col][b] 128 MB
__device__ __align__(16) float g_h[2][2][256 * 32];              // [buf][dir][k][b]
__device__ __align__(16) float g_hsum[512 * 32];                 // [feat][b]
__device__ __align__(16) float g_fc[256 * 32];                   // [j][b]
__device__ unsigned g_arrive[2];
__device__ unsigned g_gen[2];
__device__ __align__(128) unsigned g_flags[2][64];               // monotonic h publish counters
__device__ __align__(128) unsigned g_gready[2][128][32];         // gate tile counters (reset per launch)

// ---------------- f32x2 helpers (exact fp32; k1) ----------------
__device__ __forceinline__ u64 pk(float lo, float hi) {
    u64 r; asm("mov.b64 %0, {%1, %2};" : "=l"(r) : "f"(lo), "f"(hi)); return r;
}
__device__ __forceinline__ u64 dupf(float v) {
    u64 r; asm("mov.b64 %0, {%1, %1};" : "=l"(r) : "f"(v)); return r;
}
__device__ __forceinline__ void fma2(u64& d, u64 a, u64 b) {
    asm("fma.rn.f32x2 %0, %1, %2, %0;" : "+l"(d) : "l"(a), "l"(b));
}
__device__ __forceinline__ float2 upk(u64 v) {
    float2 f; asm("mov.b64 {%0, %1}, %2;" : "=f"(f.x), "=f"(f.y) : "l"(v)); return f;
}

__device__ __forceinline__ float sigf(float x) { return 1.0f / (1.0f + __expf(-x)); }
__device__ __forceinline__ float tanh_fast(float x) {
    float e = __expf(2.0f * x);
    return 1.0f - 2.0f / (e + 1.0f);
}

__device__ __forceinline__ unsigned ldacq(const unsigned* p) {
    unsigned v;
    asm volatile("ld.acquire.gpu.global.u32 %0, [%1];" : "=r"(v) : "l"(p) : "memory");
    return v;
}
__device__ __forceinline__ void red_release_add1(unsigned* p) {
    asm volatile("red.release.gpu.global.add.u32 [%0], 1;" :: "l"(p) : "memory");
}

__device__ __forceinline__ void mma16816(float* c, const unsigned* a, unsigned b0, unsigned b1) {
    asm volatile(
        "mma.sync.aligned.m16n8k16.row.col.f32.bf16.bf16.f32 "
        "{%0,%1,%2,%3}, {%4,%5,%6,%7}, {%8,%9}, {%0,%1,%2,%3};"
        : "+f"(c[0]), "+f"(c[1]), "+f"(c[2]), "+f"(c[3])
        : "r"(a[0]), "r"(a[1]), "r"(a[2]), "r"(a[3]), "r"(b0), "r"(b1));
}
__device__ __forceinline__ void cpa16(const void* sptr, const void* gptr) {
    unsigned sa = (unsigned)__cvta_generic_to_shared(sptr);
    asm volatile("cp.async.cg.shared.global [%0], [%1], 16;" :: "r"(sa), "l"(gptr));
}
__device__ __forceinline__ void bf16split(float v, __nv_bfloat16& h, __nv_bfloat16& l) {
    h = __float2bfloat16(v);
    l = __float2bfloat16(v - __bfloat162float(h));
}

// Sense-reversing barrier among the 64 recurrence CTAs of one direction.
__device__ __forceinline__ void dir_barrier(int dir, unsigned ncta) {
    __syncthreads();
    if (threadIdx.x == 0) {
        volatile unsigned* gen = &g_gen[dir];
        unsigned old = *gen;
        __threadfence();
        unsigned a = atomicAdd(&g_arrive[dir], 1u);
        if (a == ncta - 1u) {
            g_arrive[dir] = 0u;
            __threadfence();
            atomicExch((unsigned*)&g_gen[dir], old + 1u);
        } else {
            while (*gen == old) { }
        }
        __threadfence();
    }
    __syncthreads();
}

// ---------------- kernel 1: z = relu(emb[x] @ W_in + b_in) -> bf16 hi/lo (R12 scalar) ----
__global__ void k1_embed(const float* __restrict__ emb, const float* __restrict__ Win,
                         const float* __restrict__ bin, const int* __restrict__ x) {
    __shared__ float As[12][68];
    __shared__ float Bs[12][68];
    __shared__ int   xid[64];
    int tid = threadIdx.x;
    int r0 = blockIdx.x * 64;
    int c0 = blockIdx.y * 64;
    if (tid < 64) {
        int r = r0 + tid;
        int b = r & 31, t = r >> 5;
        xid[tid] = x[b * T_ + t];
    }
    __syncthreads();
    int tx = tid & 15, ty = tid >> 4;
    u64 acc2[2][4];
#pragma unroll
    for (int p = 0; p < 2; ++p)
#pragma unroll
        for (int j = 0; j < 4; ++j) acc2[p][j] = 0ULL;

    int ar = tid >> 2, ag = (tid & 3) * 3;
    int bc = tid & 63, bg = (tid >> 6) * 3;

    for (int k0 = 0; k0 < WDIM_; k0 += 12) {
        const float* ep = emb + (size_t)xid[ar] * WDIM_ + k0 + ag;
        As[ag + 0][ar] = ep[0];
        As[ag + 1][ar] = ep[1];
        As[ag + 2][ar] = ep[2];
#pragma unroll
        for (int j = 0; j < 3; ++j)
            Bs[bg + j][bc] = Win[(size_t)(k0 + bg + j) * H_ + c0 + bc];
        __syncthreads();
#pragma unroll
        for (int kk = 0; kk < 12; ++kk) {
            float4 a  = *(const float4*)&As[kk][ty * 4];
            float4 bv = *(const float4*)&Bs[kk][tx * 4];
            u64 ap0 = pk(a.x, a.y), ap1 = pk(a.z, a.w);
            u64 bd0 = dupf(bv.x), bd1 = dupf(bv.y), bd2 = dupf(bv.z), bd3 = dupf(bv.w);
            fma2(acc2[0][0], ap0, bd0); fma2(acc2[0][1], ap0, bd1);
            fma2(acc2[0][2], ap0, bd2); fma2(acc2[0][3], ap0, bd3);
            fma2(acc2[1][0], ap1, bd0); fma2(acc2[1][1], ap1, bd1);
            fma2(acc2[1][2], ap1, bd2); fma2(acc2[1][3], ap1, bd3);
        }
        __syncthreads();
    }
    float bj[4];
#pragma unroll
    for (int j = 0; j < 4; ++j) bj[j] = bin[c0 + tx * 4 + j];
#pragma unroll
    for (int p = 0; p < 2; ++p) {
        float2 uu[4];
#pragma unroll
        for (int j = 0; j < 4; ++j) uu[j] = upk(acc2[p][j]);
        float vr[2][4];
#pragma unroll
        for (int j = 0; j < 4; ++j) {
            vr[0][j] = fmaxf(uu[j].x + bj[j], 0.0f);
            vr[1][j] = fmaxf(uu[j].y + bj[j], 0.0f);
        }
#pragma unroll
        for (int q = 0; q < 2; ++q) {
            int r = r0 + ty * 4 + p * 2 + q;
            size_t base = (size_t)r * 256 + c0 + tx * 4;
            __nv_bfloat16 h[4], l[4];
#pragma unroll
            for (int j = 0; j < 4; ++j) bf16split(vr[q][j], h[j], l[j]);
            *(__nv_bfloat162*)&g_zhi[base]     = __nv_bfloat162{h[0], h[1]};
            *(__nv_bfloat162*)&g_zhi[base + 2] = __nv_bfloat162{h[2], h[3]};
            *(__nv_bfloat162*)&g_zlo[base]     = __nv_bfloat162{l[0], l[1]};
            *(__nv_bfloat162*)&g_zlo[base + 2] = __nv_bfloat162{l[2], l[3]};
        }
    }
}

// ---------------- kernel 2w: split/transpose Wih -> g_wt[dir][part][c][k] ----------------
__global__ void k2w_conv(const float* __restrict__ Wf, const float* __restrict__ Wb) {
    int gid = blockIdx.x * 256 + threadIdx.x;
    int k = gid & 255;
    int c = (gid >> 8) & 1023;
    int dir = gid >> 18;
    float w = (dir ? Wb : Wf)[(size_t)k * 1024 + c];
    __nv_bfloat16 hi, lo;
    bf16split(w, hi, lo);
    g_wt[dir][0][c][k] = hi;
    g_wt[dir][1][c][k] = lo;
}

// ---------------- fused kernel: gate GEMM workers + BiLSTM recurrence ----------------
// grid 256: bid 0..127 = GEMM workers (scheduled first), bid 128..255 = recurrence CTAs.
// Worker i: dir=i>>6, by=(i&63)&7, bxg=(i&63)>>3; 16 tiles j: bx = bxg+8j (dir0) or
// reversed (dir1). After each tile: release-add g_gready[dir][bx].
// Recurrence: R12 k3 + per-step gate-readiness wait (cached per 4-step group),
// gpre prefetch moved after syncA, tanh via __expf identity.
#define BST 40
#define AST   522
#define AST_W 261
__global__ void __launch_bounds__(256, 2)
k23_fused(const float* __restrict__ Whhf, const float* __restrict__ Whhb,
          const int* __restrict__ mask,
          const float* __restrict__ blf, const float* __restrict__ blb) {
    __shared__ __align__(16) unsigned char smraw[40960];

    int bid = blockIdx.x;
    int tid = threadIdx.x;
    int wid = tid >> 5, lane = tid & 31;
    int g = lane >> 2, tg = lane & 3;

    if (bid < 128) {
        // ================= GEMM worker =================
        __nv_bfloat16* smb = (__nv_bfloat16*)smraw;   // [st][ab][128*BST]
        float* Sc = (float*)smraw;
        int dir = bid >> 6;
        int widx = bid & 63;
        int by = widx & 7, bxg = widx >> 3;
        int wm = wid & 3, wn = wid >> 2;
        int m0 = wm * 32, n0 = wn * 64;
        int row2 = tid >> 1, half = tid & 1;
        int c0 = by * 128;
        const float* bl = dir ? blb : blf;

        for (int j = 0; j < 16; ++j) {
            int bx = dir == 0 ? (bxg + 8 * j) : (127 - (bxg + 8 * j));
            int r0 = bx * 128;

            float c[2][8][4];
#pragma unroll
            for (int mi = 0; mi < 2; ++mi)
#pragma unroll
                for (int ni = 0; ni < 8; ++ni)
#pragma unroll
                    for (int q = 0; q < 4; ++q) c[mi][ni][q] = 0.0f;

            auto prefetch = [&](int it) {
                int seg = it >> 3, chunk = it & 7;
                const __nv_bfloat16* Ag = (seg < 2) ? g_zhi : g_zlo;
                const __nv_bfloat16* Bg = &g_wt[dir][(seg == 1) ? 1 : 0][c0][0];
                int st = it & 1;
                const __nv_bfloat16* as = Ag + (size_t)(r0 + row2) * 256 + chunk * 32 + half * 16;
                const __nv_bfloat16* bs = Bg + (size_t)row2 * 256 + chunk * 32 + half * 16;
                __nv_bfloat16* ad = smb + (st * 2 + 0) * (128 * BST) + row2 * BST + half * 16;
                __nv_bfloat16* bd = smb + (st * 2 + 1) * (128 * BST) + row2 * BST + half * 16;
                cpa16(ad, as); cpa16(ad + 8, as + 8);
                cpa16(bd, bs); cpa16(bd + 8, bs + 8);
                asm volatile("cp.async.commit_group;" ::: "memory");
            };

            prefetch(0);
            for (int it = 0; it < 24; ++it) {
                asm volatile("cp.async.wait_group 0;" ::: "memory");
                __syncthreads();
                if (it < 23) prefetch(it + 1);
                int st = it & 1;
                const __nv_bfloat16* As = smb + (st * 2 + 0) * (128 * BST);
                const __nv_bfloat16* Bs = smb + (st * 2 + 1) * (128 * BST);
#pragma unroll
                for (int ks = 0; ks < 2; ++ks) {
                    int k1 = ks * 16;
                    unsigned a[2][4];
#pragma unroll
                    for (int mi = 0; mi < 2; ++mi) {
                        const __nv_bfloat16* ab = As + (m0 + mi * 16 + g) * BST + k1 + tg * 2;
                        a[mi][0] = *(const unsigned*)ab;
                        a[mi][1] = *(const unsigned*)(ab + 8 * BST);
                        a[mi][2] = *(const unsigned*)(ab + 8);
                        a[mi][3] = *(const unsigned*)(ab + 8 * BST + 8);
                    }
#pragma unroll
                    for (int ni = 0; ni < 8; ++ni) {
                        const __nv_bfloat16* bb = Bs + (n0 + ni * 8 + g) * BST + k1 + tg * 2;
                        unsigned b0 = *(const unsigned*)bb;
                        unsigned b1 = *(const unsigned*)(bb + 8);
                        mma16816(c[0][ni], a[0], b0, b1);
                        mma16816(c[1][ni], a[1], b0, b1);
                    }
                }
            }
            __syncthreads();   // MMAs done before Sc (alias) writes

            int t = bx * 4 + wm;
            float* myS = Sc + wid * (8 * 33);
            size_t gbase = (size_t)(dir * 512 + t) * (1024 * 32);
#pragma unroll
            for (int ni = 0; ni < 8; ++ni) {
#pragma unroll
                for (int mi = 0; mi < 2; ++mi)
#pragma unroll
                    for (int q = 0; q < 4; ++q) {
                        int col_local = tg * 2 + (q & 1);
                        int row_local = mi * 16 + g + ((q >> 1) ? 8 : 0);
                        myS[col_local * 33 + row_local] = c[mi][ni][q];
                    }
                __syncwarp();
#pragma unroll
                for (int col = 0; col < 8; ++col) {
                    int cg = c0 + n0 + ni * 8 + col;
                    float v = myS[col * 33 + lane] + __ldg(&bl[cg]);
                    g_gates[gbase + (size_t)cg * 32 + lane] = v;
                }
                __syncwarp();
            }
            __syncthreads();   // all stores done before counter bump / next prefetch
            if (tid == 0) red_release_add1(&g_gready[dir][bx][0]);
        }
        return;
    }

    // ================= recurrence CTA =================
    __nv_bfloat16* As = (__nv_bfloat16*)smraw;
    float* red = (float*)smraw;
    unsigned* Asw = (unsigned*)smraw;

    int cta   = bid - 128;
    int dir   = cta >> 6;
    int slice = cta & 63;
    int u0    = slice << 2;
    const float* Whh = dir ? Whhb : Whhf;
    int kbase = wid << 5;

    unsigned bhi[2][2][2], blo[2][2][2];
#pragma unroll
    for (int kt = 0; kt < 2; ++kt)
#pragma unroll
        for (int nt = 0; nt < 2; ++nt)
#pragma unroll
            for (int r = 0; r < 2; ++r) {
                int n  = nt * 8 + g;
                int gc = (n >> 2) * 256 + u0 + (n & 3);
                int k  = kbase + kt * 16 + tg * 2 + r * 8;
                float w0 = Whh[(size_t)k * 1024 + gc];
                float w1 = Whh[(size_t)(k + 1) * 1024 + gc];
                __nv_bfloat16 h0, l0, h1, l1;
                bf16split(w0, h0, l0);
                bf16split(w1, h1, l1);
                __nv_bfloat162 ph{h0, h1}, pl{l0, l1};
                bhi[kt][nt][r] = *(unsigned*)&ph;
                blo[kt][nt][r] = *(unsigned*)&pl;
            }

    int u = tid >> 5;
    int b = tid & 31;
    float c_reg = 0.0f, h_reg = 0.0f, hsum_reg = 0.0f;
    if (tid < 128) g_h[0][dir][(u0 + u) * 32 + b] = 0.0f;

    unsigned base = 0;
    const unsigned* myflag = 0;
    if (tid >= 192) {
        myflag = &g_flags[dir][tid - 192];
        base = ldacq(myflag);
    }
    dir_barrier(dir, 64);

    unsigned* pubflag = &g_flags[dir][slice];
    int kp  = lane >> 3;
    int b0c = (lane & 7) * 4;
    int gdone = -1;   // last gate-group known ready (tid>=192 threads)

    for (int t = 0; t < T_; ++t) {
        int cur = t & 1, nxt = cur ^ 1;
        int tt = dir ? (T_ - 1 - t) : t;

        if (tid >= 192) {
            int grp = tt >> 2;
            if (grp != gdone) {
                const unsigned* gc = &g_gready[dir][grp][0];
                while (ldacq(gc) < 8u) { }
                gdone = grp;
            }
            unsigned need = 128u * (unsigned)t;
            while (ldacq(myflag) - base < need) { }
        }
        __syncthreads();   // syncA: gates[tt] + h(t) visible; red reads (prev) done

        // gpre prefetch (after gates ready); consumed ~1500 cyc later after sync2
        float gpre0 = 0.f, gpre1 = 0.f, gpre2 = 0.f, gpre3 = 0.f, mval = 0.f;
        if (tid < 128) {
            const float* gp = g_gates + (size_t)(dir * 512 + tt) * (1024 * 32);
            gpre0 = gp[(0 * 256 + u0 + u) * 32 + b];
            gpre1 = gp[(1 * 256 + u0 + u) * 32 + b];
            gpre2 = gp[(2 * 256 + u0 + u) * 32 + b];
            gpre3 = gp[(3 * 256 + u0 + u) * 32 + b];
            mval  = (float)mask[b * T_ + tt];
        }

        // copy + convert: warp converts its own 32 k-rows
#pragma unroll
        for (int p = 0; p < 4; ++p) {
            int k = kbase + p * 8 + kp * 2;
            float4 ha = __ldcg((const float4*)&g_h[cur][dir][k * 32 + b0c]);
            float4 hb = __ldcg((const float4*)&g_h[cur][dir][(k + 1) * 32 + b0c]);
            float va[4] = {ha.x, ha.y, ha.z, ha.w};
            float vb[4] = {hb.x, hb.y, hb.z, hb.w};
#pragma unroll
            for (int j = 0; j < 4; ++j) {
                unsigned ba = __float_as_uint(va[j]);
                unsigned bb = __float_as_uint(vb[j]);
                unsigned hiw = __byte_perm(ba, bb, 0x7632);
                float ra = va[j] - __uint_as_float(ba & 0xFFFF0000u);
                float rb = vb[j] - __uint_as_float(bb & 0xFFFF0000u);
                unsigned low;
                asm("cvt.rn.bf16x2.f32 %0, %1, %2;" : "=r"(low) : "f"(rb), "f"(ra));
                int row = b0c + j;
                Asw[row * AST_W + (k >> 1)]       = hiw;
                Asw[row * AST_W + 128 + (k >> 1)] = low;
            }
        }
        __syncthreads();   // syncB

        float c[2][2][4];
#pragma unroll
        for (int mi = 0; mi < 2; ++mi)
#pragma unroll
            for (int ni = 0; ni < 2; ++ni)
#pragma unroll
                for (int q = 0; q < 4; ++q) c[mi][ni][q] = 0.0f;

        unsigned afr[2][2][4];
#pragma unroll
        for (int kt = 0; kt < 2; ++kt)
#pragma unroll
            for (int mi = 0; mi < 2; ++mi) {
                const __nv_bfloat16* ab = As + (mi * 16 + g) * AST + kbase + kt * 16 + tg * 2;
                afr[kt][mi][0] = *(const unsigned*)ab;
                afr[kt][mi][1] = *(const unsigned*)(ab + 8 * AST);
                afr[kt][mi][2] = *(const unsigned*)(ab + 8);
                afr[kt][mi][3] = *(const unsigned*)(ab + 8 * AST + 8);
            }
#pragma unroll
        for (int kt = 0; kt < 2; ++kt)
#pragma unroll
            for (int mi = 0; mi < 2; ++mi)
#pragma unroll
                for (int ni = 0; ni < 2; ++ni) {
                    mma16816(c[mi][ni], afr[kt][mi], bhi[kt][ni][0], bhi[kt][ni][1]);
                    mma16816(c[mi][ni], afr[kt][mi], blo[kt][ni][0], blo[kt][ni][1]);
                }
#pragma unroll
        for (int kt = 0; kt < 2; ++kt)
#pragma unroll
            for (int mi = 0; mi < 2; ++mi) {
                const __nv_bfloat16* ab = As + (mi * 16 + g) * AST + 256 + kbase + kt * 16 + tg * 2;
                afr[kt][mi][0] = *(const unsigned*)ab;
                afr[kt][mi][1] = *(const unsigned*)(ab + 8 * AST);
                afr[kt][mi][2] = *(const unsigned*)(ab + 8);
                afr[kt][mi][3] = *(const unsigned*)(ab + 8 * AST + 8);
            }
#pragma unroll
        for (int kt = 0; kt < 2; ++kt)
#pragma unroll
            for (int mi = 0; mi < 2; ++mi)
#pragma unroll
                for (int ni = 0; ni < 2; ++ni)
                    mma16816(c[mi][ni], afr[kt][mi], bhi[kt][ni][0], bhi[kt][ni][1]);

        __syncthreads();   // sync1
#pragma unroll
        for (int mi = 0; mi < 2; ++mi)
#pragma unroll
            for (int ni = 0; ni < 2; ++ni)
#pragma unroll
                for (int q = 0; q < 4; ++q) {
                    int row = mi * 16 + g + ((q >> 1) ? 8 : 0);
                    int col = ni * 8 + tg * 2 + (q & 1);
                    red[wid * 528 + col * 33 + row] = c[mi][ni][q];
                }
        __syncthreads();   // sync2

        if (tid < 128) {
            float z0 = gpre0, z1 = gpre1, z2 = gpre2, z3 = gpre3;
#pragma unroll
            for (int w = 0; w < 8; ++w) {
                const float* rp = red + w * 528 + b;
                z0 += rp[(0 + u) * 33];
                z1 += rp[(4 + u) * 33];
                z2 += rp[(8 + u) * 33];
                z3 += rp[(12 + u) * 33];
            }
            float ig = sigf(z0), fg = sigf(z1);
            float gg = tanh_fast(z2), og = sigf(z3);
            float cn = fg * c_reg + ig * gg;
            float hn = og * tanh_fast(cn);
            c_reg = mval * cn + (1.0f - mval) * c_reg;
            h_reg = mval * hn + (1.0f - mval) * h_reg;
            hsum_reg += mval * h_reg;
            g_h[nxt][dir][(u0 + u) * 32 + b] = h_reg;
            red_release_add1(pubflag);
        }
    }
    if (tid < 128) g_hsum[((dir << 8) + u0 + u) * 32 + b] = hsum_reg;

    // reset gate counters for next launch (after all polls in this dir completed)
    dir_barrier(dir, 64);
    if (tid == 0) {
        g_gready[dir][2 * slice][0]     = 0;
        g_gready[dir][2 * slice + 1][0] = 0;
    }
}

// ---------------- kernel 4a: fc_hidden[j][b], one CTA per j ----------------
__global__ void k4a_fc(const float* __restrict__ Wfc, const float* __restrict__ bfc,
                       const int* __restrict__ lengths) {
    __shared__ float redsm[8][32];
    int j = blockIdx.x;
    int tid = threadIdx.x;
    int w = tid >> 5, lane = tid & 31;
    float acc = 0.0f;
    int f0 = w * 64;
#pragma unroll 8
    for (int f = f0; f < f0 + 64; ++f)
        acc += g_hsum[f * 32 + lane] * Wfc[(size_t)f * 256 + j];
    redsm[w][lane] = acc;
    __syncthreads();
    if (w == 0) {
        float s = 0.0f;
#pragma unroll
        for (int q = 0; q < 8; ++q) s += redsm[q][lane];
        float invlen = 1.0f / (float)lengths[lane];
        g_fc[j * 32 + lane] = fmaxf(s * invlen + bfc[j], 0.0f);
    }
}

// ---------------- kernel 4b: logits ----------------
__global__ void k4b_out(const float* __restrict__ Wout, const float* __restrict__ bout,
                        float* __restrict__ out) {
    int t = threadIdx.x;
    int b = t >> 1, lab = t & 1;
    float s = bout[lab];
#pragma unroll 8
    for (int j = 0; j < 256; ++j)
        s += g_fc[j * 32 + b] * Wout[j * 2 + lab];
    out[b * 2 + lab] = s;
}

// ---------------- launch ----------------
extern "C" void kernel_launch(void* const* d_in, const int* in_sizes, int n_in,
                              void* d_out, int out_size) {
    const float* emb  = (const float*)d_in[0];
    const float* Win  = (const float*)d_in[1];
    const float* bin  = (const float*)d_in[2];
    const float* Wihf = (const float*)d_in[3];
    const float* Whhf = (const float*)d_in[4];
    const float* blf  = (const float*)d_in[5];
    const float* Wihb = (const float*)d_in[6];
    const float* Whhb = (const float*)d_in[7];
    const float* blb  = (const float*)d_in[8];
    const float* Wfc  = (const float*)d_in[9];
    const float* bfc  = (const float*)d_in[10];
    const float* Wout = (const float*)d_in[11];
    const float* bout = (const float*)d_in[12];
    const int*   x    = (const int*)d_in[13];
    const int*   mask = (const int*)d_in[14];
    const int*   len  = (const int*)d_in[15];
    float* out = (float*)d_out;

    k1_embed<<<dim3(256, 4), 256>>>(emb, Win, bin, x);
    k2w_conv<<<2048, 256>>>(Wihf, Wihb);
    k23_fused<<<256, 256>>>(Whhf, Whhb, mask, blf, blb);
    k4a_fc<<<256, 256>>>(Wfc, bfc, len);
    k4b_out<<<1, 64>>>(Wout, bout, out);
}

// round 15
// speedup vs baseline: 1.1297x; 1.1297x over previous
#include <cuda_runtime.h>
#include <cuda_bf16.h>
#include <cstdint>

#define B_    32
#define T_    512
#define H_    256
#define WDIM_ 300

typedef unsigned long long u64;

// ---------------- scratch (device globals; no allocation allowed) ----------------
__device__ __align__(16) __nv_bfloat16 g_zhi[16384 * 256];       // z split hi  [r][k]
__device__ __align__(16) __nv_bfloat16 g_zlo[16384 * 256];       // z split lo  [r][k]
__device__ __align__(16) __nv_bfloat16 g_wt[2][2][1024][256];    // [dir][part][c][k]
__device__ __align__(16) float g_gates[2 * 512 * 1024 * 32];     // [dir][t][col][b] 128 MB
__device__ __align__(16) float g_h[2][2][256 * 32];              // [buf][dir][k][b]
__device__ __align__(16) float g_hsum[512 * 32];                 // [feat][b]
__device__ __align__(16) float g_fc[256 * 32];                   // [j][b]
__device__ unsigned g_arrive[2];
__device__ unsigned g_gen[2];
__device__ __align__(128) unsigned g_flags[2][64];               // monotonic publish counters

// ---------------- f32x2 helpers (exact fp32 semantics; used in k1) ----------------
__device__ __forceinline__ u64 pk(float lo, float hi) {
    u64 r; asm("mov.b64 %0, {%1, %2};" : "=l"(r) : "f"(lo), "f"(hi)); return r;
}
__device__ __forceinline__ u64 dupf(float v) {
    u64 r; asm("mov.b64 %0, {%1, %1};" : "=l"(r) : "f"(v)); return r;
}
__device__ __forceinline__ void fma2(u64& d, u64 a, u64 b) {
    asm("fma.rn.f32x2 %0, %1, %2, %0;" : "+l"(d) : "l"(a), "l"(b));
}
__device__ __forceinline__ float2 upk(u64 v) {
    float2 f; asm("mov.b64 {%0, %1}, %2;" : "=f"(f.x), "=f"(f.y) : "l"(v)); return f;
}

__device__ __forceinline__ float sigf(float x) { return 1.0f / (1.0f + __expf(-x)); }
__device__ __forceinline__ float tanh_fast(float x) {
    float e = __expf(2.0f * x);
    return 1.0f - 2.0f / (e + 1.0f);
}

__device__ __forceinline__ unsigned ldacq(const unsigned* p) {
    unsigned v;
    asm volatile("ld.acquire.gpu.global.u32 %0, [%1];" : "=r"(v) : "l"(p) : "memory");
    return v;
}
__device__ __forceinline__ void red_release_add1(unsigned* p) {
    asm volatile("red.release.gpu.global.add.u32 [%0], 1;" :: "l"(p) : "memory");
}

// warp-level bf16 MMA (sm_80+ baseline; works on compute_103)
__device__ __forceinline__ void mma16816(float* c, const unsigned* a, unsigned b0, unsigned b1) {
    asm volatile(
        "mma.sync.aligned.m16n8k16.row.col.f32.bf16.bf16.f32 "
        "{%0,%1,%2,%3}, {%4,%5,%6,%7}, {%8,%9}, {%0,%1,%2,%3};"
        : "+f"(c[0]), "+f"(c[1]), "+f"(c[2]), "+f"(c[3])
        : "r"(a[0]), "r"(a[1]), "r"(a[2]), "r"(a[3]), "r"(b0), "r"(b1));
}

// cp.async 16B (sm_80+ baseline)
__device__ __forceinline__ void cpa16(const void* sptr, const void* gptr) {
    unsigned sa = (unsigned)__cvta_generic_to_shared(sptr);
    asm volatile("cp.async.cg.shared.global [%0], [%1], 16;" :: "r"(sa), "l"(gptr));
}

__device__ __forceinline__ void bf16split(float v, __nv_bfloat16& h, __nv_bfloat16& l) {
    h = __float2bfloat16(v);
    l = __float2bfloat16(v - __bfloat162float(h));
}

// Sense-reversing barrier among the 64 CTAs of one direction (used ONCE at start of k3).
__device__ __forceinline__ void dir_barrier(int dir, unsigned ncta) {
    __syncthreads();
    if (threadIdx.x == 0) {
        volatile unsigned* gen = &g_gen[dir];
        unsigned old = *gen;
        __threadfence();
        unsigned a = atomicAdd(&g_arrive[dir], 1u);
        if (a == ncta - 1u) {
            g_arrive[dir] = 0u;
            __threadfence();
            atomicExch((unsigned*)&g_gen[dir], old + 1u);
        } else {
            while (*gen == old) { }
        }
        __threadfence();
    }
    __syncthreads();
}

// ---------------- kernel 1: z = relu(emb[x] @ W_in + b_in) -> bf16 hi/lo ----------------
__global__ void k1_embed(const float* __restrict__ emb, const float* __restrict__ Win,
                         const float* __restrict__ bin, const int* __restrict__ x) {
    __shared__ float As[12][68];
    __shared__ float Bs[12][68];
    __shared__ int   xid[64];
    int tid = threadIdx.x;
    int r0 = blockIdx.x * 64;
    int c0 = blockIdx.y * 64;
    if (tid < 64) {
        int r = r0 + tid;
        int b = r & 31, t = r >> 5;
        xid[tid] = x[b * T_ + t];
    }
    __syncthreads();
    int tx = tid & 15, ty = tid >> 4;
    u64 acc2[2][4];
#pragma unroll
    for (int p = 0; p < 2; ++p)
#pragma unroll
        for (int j = 0; j < 4; ++j) acc2[p][j] = 0ULL;

    int ar = tid >> 2, ag = (tid & 3) * 3;
    int bc = tid & 63, bg = (tid >> 6) * 3;

    for (int k0 = 0; k0 < WDIM_; k0 += 12) {
        const float* ep = emb + (size_t)xid[ar] * WDIM_ + k0 + ag;
        As[ag + 0][ar] = ep[0];
        As[ag + 1][ar] = ep[1];
        As[ag + 2][ar] = ep[2];
#pragma unroll
        for (int j = 0; j < 3; ++j)
            Bs[bg + j][bc] = Win[(size_t)(k0 + bg + j) * H_ + c0 + bc];
        __syncthreads();
#pragma unroll
        for (int kk = 0; kk < 12; ++kk) {
            float4 a  = *(const float4*)&As[kk][ty * 4];
            float4 bv = *(const float4*)&Bs[kk][tx * 4];
            u64 ap0 = pk(a.x, a.y), ap1 = pk(a.z, a.w);
            u64 bd0 = dupf(bv.x), bd1 = dupf(bv.y), bd2 = dupf(bv.z), bd3 = dupf(bv.w);
            fma2(acc2[0][0], ap0, bd0); fma2(acc2[0][1], ap0, bd1);
            fma2(acc2[0][2], ap0, bd2); fma2(acc2[0][3], ap0, bd3);
            fma2(acc2[1][0], ap1, bd0); fma2(acc2[1][1], ap1, bd1);
            fma2(acc2[1][2], ap1, bd2); fma2(acc2[1][3], ap1, bd3);
        }
        __syncthreads();
    }
    float bj[4];
#pragma unroll
    for (int j = 0; j < 4; ++j) bj[j] = bin[c0 + tx * 4 + j];
#pragma unroll
    for (int p = 0; p < 2; ++p) {
        float2 uu[4];
#pragma unroll
        for (int j = 0; j < 4; ++j) uu[j] = upk(acc2[p][j]);
        float vr[2][4];
#pragma unroll
        for (int j = 0; j < 4; ++j) {
            vr[0][j] = fmaxf(uu[j].x + bj[j], 0.0f);
            vr[1][j] = fmaxf(uu[j].y + bj[j], 0.0f);
        }
#pragma unroll
        for (int q = 0; q < 2; ++q) {
            int r = r0 + ty * 4 + p * 2 + q;
            size_t base = (size_t)r * 256 + c0 + tx * 4;
            __nv_bfloat16 h[4], l[4];
#pragma unroll
            for (int j = 0; j < 4; ++j) bf16split(vr[q][j], h[j], l[j]);
            *(__nv_bfloat162*)&g_zhi[base]     = __nv_bfloat162{h[0], h[1]};
            *(__nv_bfloat162*)&g_zhi[base + 2] = __nv_bfloat162{h[2], h[3]};
            *(__nv_bfloat162*)&g_zlo[base]     = __nv_bfloat162{l[0], l[1]};
            *(__nv_bfloat162*)&g_zlo[base + 2] = __nv_bfloat162{l[2], l[3]};
        }
    }
}

// ---------------- kernel 2w: split/transpose Wih -> g_wt[dir][part][c][k] ----------------
__global__ void k2w_conv(const float* __restrict__ Wf, const float* __restrict__ Wb) {
    int gid = blockIdx.x * 256 + threadIdx.x;     // 2*1024*256 total
    int k = gid & 255;
    int c = (gid >> 8) & 1023;
    int dir = gid >> 18;
    float w = (dir ? Wb : Wf)[(size_t)k * 1024 + c];
    __nv_bfloat16 hi, lo;
    bf16split(w, hi, lo);
    g_wt[dir][0][c][k] = hi;
    g_wt[dir][1][c][k] = lo;
}

// ---------------- kernel 2: pipelined HMMA bf16-split GEMM: gates = z @ Wih + bl ----------
// CTA tile 128x128, K-chunk 32, two cp.async stages, one barrier per chunk.
#define BST 40   // smem row stride in bf16 elements
__global__ void __launch_bounds__(256) k2_hmma(const float* __restrict__ blf,
                                               const float* __restrict__ blb) {
    __shared__ __align__(16) __nv_bfloat16 sm[2][2][128 * BST];  // 40960 B
    float* Sc = (float*)sm;                                      // epilogue alias

    int tid = threadIdx.x;
    int wid = tid >> 5, lane = tid & 31;
    int g = lane >> 2, tg = lane & 3;
    int wm = wid & 3, wn = wid >> 2;
    int bx = blockIdx.x, by = blockIdx.y;
    int dir = by >> 3;
    int c0  = (by & 7) * 128;
    int r0  = bx * 128;
    int row2 = tid >> 1, half = tid & 1;

    float c[2][8][4];
#pragma unroll
    for (int mi = 0; mi < 2; ++mi)
#pragma unroll
        for (int ni = 0; ni < 8; ++ni)
#pragma unroll
            for (int q = 0; q < 4; ++q) c[mi][ni][q] = 0.0f;

    int m0 = wm * 32;
    int n0 = wn * 64;

    auto prefetch = [&](int it) {
        int seg = it >> 3, chunk = it & 7;
        const __nv_bfloat16* Ag = (seg < 2) ? g_zhi : g_zlo;
        const __nv_bfloat16* Bg = &g_wt[dir][(seg == 1) ? 1 : 0][c0][0];
        int st = it & 1;
        const __nv_bfloat16* as = Ag + (size_t)(r0 + row2) * 256 + chunk * 32 + half * 16;
        const __nv_bfloat16* bs = Bg + (size_t)row2 * 256 + chunk * 32 + half * 16;
        __nv_bfloat16* ad = &sm[st][0][row2 * BST + half * 16];
        __nv_bfloat16* bd = &sm[st][1][row2 * BST + half * 16];
        cpa16(ad, as); cpa16(ad + 8, as + 8);
        cpa16(bd, bs); cpa16(bd + 8, bs + 8);
        asm volatile("cp.async.commit_group;" ::: "memory");
    };

    prefetch(0);
    for (int it = 0; it < 24; ++it) {
        asm volatile("cp.async.wait_group 0;" ::: "memory");
        __syncthreads();
        if (it < 23) prefetch(it + 1);
        int st = it & 1;
        const __nv_bfloat16* As = sm[st][0];
        const __nv_bfloat16* Bs = sm[st][1];
#pragma unroll
        for (int ks = 0; ks < 2; ++ks) {
            int k1 = ks * 16;
            unsigned a[2][4];
#pragma unroll
            for (int mi = 0; mi < 2; ++mi) {
                const __nv_bfloat16* ab = As + (m0 + mi * 16 + g) * BST + k1 + tg * 2;
                a[mi][0] = *(const unsigned*)ab;
                a[mi][1] = *(const unsigned*)(ab + 8 * BST);
                a[mi][2] = *(const unsigned*)(ab + 8);
                a[mi][3] = *(const unsigned*)(ab + 8 * BST + 8);
            }
#pragma unroll
            for (int ni = 0; ni < 8; ++ni) {
                const __nv_bfloat16* bb = Bs + (n0 + ni * 8 + g) * BST + k1 + tg * 2;
                unsigned b0 = *(const unsigned*)bb;
                unsigned b1 = *(const unsigned*)(bb + 8);
                mma16816(c[0][ni], a[0], b0, b1);
                mma16816(c[1][ni], a[1], b0, b1);
            }
        }
    }
    __syncthreads();   // all MMAs done before Sc (alias) writes

    const float* bl = dir ? blb : blf;
    int t = bx * 4 + wm;
    float* myS = Sc + wid * (8 * 33);
    size_t gbase = (size_t)(dir * 512 + t) * (1024 * 32);
#pragma unroll
    for (int ni = 0; ni < 8; ++ni) {
#pragma unroll
        for (int mi = 0; mi < 2; ++mi)
#pragma unroll
            for (int q = 0; q < 4; ++q) {
                int col_local = tg * 2 + (q & 1);
                int row_local = mi * 16 + g + ((q >> 1) ? 8 : 0);
                myS[col_local * 33 + row_local] = c[mi][ni][q];
            }
        __syncwarp();
#pragma unroll
        for (int col = 0; col < 8; ++col) {
            int cg = c0 + n0 + ni * 8 + col;
            float v = myS[col * 33 + lane] + __ldg(&bl[cg]);
            g_gates[gbase + (size_t)cg * 32 + lane] = v;
        }
        __syncwarp();
    }
}

// ---------------- kernel 3: persistent BiLSTM recurrence (R9 skeleton + tanh_fast) -------
#define AST   522
#define AST_W 261
__global__ void __launch_bounds__(256, 1)
k3_lstm(const float* __restrict__ Whhf, const float* __restrict__ Whhb,
        const int* __restrict__ mask) {
    __shared__ __align__(16) __nv_bfloat16 As[32 * AST];   // 33408 B
    float* red = (float*)As;
    unsigned* Asw = (unsigned*)As;

    int cta   = blockIdx.x;
    int dir   = cta >> 6;
    int slice = cta & 63;
    int u0    = slice << 2;
    const float* Whh = dir ? Whhb : Whhf;
    int tid  = threadIdx.x;
    int warp = tid >> 5, lane = tid & 31;
    int g = lane >> 2, tg = lane & 3;
    int kbase = warp << 5;

    unsigned bhi[2][2][2], blo[2][2][2];
#pragma unroll
    for (int kt = 0; kt < 2; ++kt)
#pragma unroll
        for (int nt = 0; nt < 2; ++nt)
#pragma unroll
            for (int r = 0; r < 2; ++r) {
                int n  = nt * 8 + g;
                int gc = (n >> 2) * 256 + u0 + (n & 3);
                int k  = kbase + kt * 16 + tg * 2 + r * 8;
                float w0 = Whh[(size_t)k * 1024 + gc];
                float w1 = Whh[(size_t)(k + 1) * 1024 + gc];
                __nv_bfloat16 h0, l0, h1, l1;
                bf16split(w0, h0, l0);
                bf16split(w1, h1, l1);
                __nv_bfloat162 ph{h0, h1}, pl{l0, l1};
                bhi[kt][nt][r] = *(unsigned*)&ph;
                blo[kt][nt][r] = *(unsigned*)&pl;
            }

    int u = tid >> 5;
    int b = tid & 31;
    float c_reg = 0.0f, h_reg = 0.0f, hsum_reg = 0.0f;
    if (tid < 128) g_h[0][dir][(u0 + u) * 32 + b] = 0.0f;

    unsigned base = 0;
    const unsigned* myflag = 0;
    if (tid >= 192) {
        myflag = &g_flags[dir][tid - 192];
        base = ldacq(myflag);
    }
    dir_barrier(dir, 64);

    unsigned* pubflag = &g_flags[dir][slice];
    int kp  = lane >> 3;
    int b0c = (lane & 7) * 4;

    for (int t = 0; t < T_; ++t) {
        int cur = t & 1, nxt = cur ^ 1;
        int tt = dir ? (T_ - 1 - t) : t;

        float gpre0 = 0.f, gpre1 = 0.f, gpre2 = 0.f, gpre3 = 0.f, mval = 0.f;
        if (tid < 128) {
            const float* gp = g_gates + (size_t)(dir * 512 + tt) * (1024 * 32);
            gpre0 = gp[(0 * 256 + u0 + u) * 32 + b];
            gpre1 = gp[(1 * 256 + u0 + u) * 32 + b];
            gpre2 = gp[(2 * 256 + u0 + u) * 32 + b];
            gpre3 = gp[(3 * 256 + u0 + u) * 32 + b];
            mval  = (float)mask[b * T_ + tt];
        }

        if (tid >= 192) {
            unsigned need = 128u * (unsigned)t;
            while (ldacq(myflag) - base < need) { }
        }
        __syncthreads();

#pragma unroll
        for (int p = 0; p < 4; ++p) {
            int k = kbase + p * 8 + kp * 2;
            float4 ha = __ldcg((const float4*)&g_h[cur][dir][k * 32 + b0c]);
            float4 hb = __ldcg((const float4*)&g_h[cur][dir][(k + 1) * 32 + b0c]);
            float va[4] = {ha.x, ha.y, ha.z, ha.w};
            float vb[4] = {hb.x, hb.y, hb.z, hb.w};
#pragma unroll
            for (int j = 0; j < 4; ++j) {
                unsigned ba = __float_as_uint(va[j]);
                unsigned bb = __float_as_uint(vb[j]);
                unsigned hiw = __byte_perm(ba, bb, 0x7632);
                float ra = va[j] - __uint_as_float(ba & 0xFFFF0000u);
                float rb = vb[j] - __uint_as_float(bb & 0xFFFF0000u);
                unsigned low;
                asm("cvt.rn.bf16x2.f32 %0, %1, %2;" : "=r"(low) : "f"(rb), "f"(ra));
                int row = b0c + j;
                Asw[row * AST_W + (k >> 1)]       = hiw;
                Asw[row * AST_W + 128 + (k >> 1)] = low;
            }
        }
        __syncthreads();

        float c[2][2][4];
#pragma unroll
        for (int mi = 0; mi < 2; ++mi)
#pragma unroll
            for (int ni = 0; ni < 2; ++ni)
#pragma unroll
                for (int q = 0; q < 4; ++q) c[mi][ni][q] = 0.0f;

        unsigned afr[2][2][4];
#pragma unroll
        for (int kt = 0; kt < 2; ++kt)
#pragma unroll
            for (int mi = 0; mi < 2; ++mi) {
                const __nv_bfloat16* ab = As + (mi * 16 + g) * AST + kbase + kt * 16 + tg * 2;
                afr[kt][mi][0] = *(const unsigned*)ab;
                afr[kt][mi][1] = *(const unsigned*)(ab + 8 * AST);
                afr[kt][mi][2] = *(const unsigned*)(ab + 8);
                afr[kt][mi][3] = *(const unsigned*)(ab + 8 * AST + 8);
            }
#pragma unroll
        for (int kt = 0; kt < 2; ++kt)
#pragma unroll
            for (int mi = 0; mi < 2; ++mi)
#pragma unroll
                for (int ni = 0; ni < 2; ++ni) {
                    mma16816(c[mi][ni], afr[kt][mi], bhi[kt][ni][0], bhi[kt][ni][1]);
                    mma16816(c[mi][ni], afr[kt][mi], blo[kt][ni][0], blo[kt][ni][1]);
                }
#pragma unroll
        for (int kt = 0; kt < 2; ++kt)
#pragma unroll
            for (int mi = 0; mi < 2; ++mi) {
                const __nv_bfloat16* ab = As + (mi * 16 + g) * AST + 256 + kbase + kt * 16 + tg * 2;
                afr[kt][mi][0] = *(const unsigned*)ab;
                afr[kt][mi][1] = *(const unsigned*)(ab + 8 * AST);
                afr[kt][mi][2] = *(const unsigned*)(ab + 8);
                afr[kt][mi][3] = *(const unsigned*)(ab + 8 * AST + 8);
            }
#pragma unroll
        for (int kt = 0; kt < 2; ++kt)
#pragma unroll
            for (int mi = 0; mi < 2; ++mi)
#pragma unroll
                for (int ni = 0; ni < 2; ++ni)
                    mma16816(c[mi][ni], afr[kt][mi], bhi[kt][ni][0], bhi[kt][ni][1]);

        __syncthreads();
#pragma unroll
        for (int mi = 0; mi < 2; ++mi)
#pragma unroll
            for (int ni = 0; ni < 2; ++ni)
#pragma unroll
                for (int q = 0; q < 4; ++q) {
                    int row = mi * 16 + g + ((q >> 1) ? 8 : 0);
                    int col = ni * 8 + tg * 2 + (q & 1);
                    red[warp * 528 + col * 33 + row] = c[mi][ni][q];
                }
        __syncthreads();

        if (tid < 128) {
            float z0 = gpre0, z1 = gpre1, z2 = gpre2, z3 = gpre3;
#pragma unroll
            for (int w = 0; w < 8; ++w) {
                const float* rp = red + w * 528 + b;
                z0 += rp[(0 + u) * 33];
                z1 += rp[(4 + u) * 33];
                z2 += rp[(8 + u) * 33];
                z3 += rp[(12 + u) * 33];
            }
            float ig = sigf(z0), fg = sigf(z1);
            float gg = tanh_fast(z2), og = sigf(z3);
            float cn = fg * c_reg + ig * gg;
            float hn = og * tanh_fast(cn);
            c_reg = mval * cn + (1.0f - mval) * c_reg;
            h_reg = mval * hn + (1.0f - mval) * h_reg;
            hsum_reg += mval * h_reg;
            g_h[nxt][dir][(u0 + u) * 32 + b] = h_reg;
            red_release_add1(pubflag);
        }
    }
    if (tid < 128) g_hsum[((dir << 8) + u0 + u) * 32 + b] = hsum_reg;
}

// ---------------- kernel 4a: fc_hidden[j][b], one CTA per j ----------------
__global__ void k4a_fc(const float* __restrict__ Wfc, const float* __restrict__ bfc,
                       const int* __restrict__ lengths) {
    __shared__ float redsm[8][32];
    int j = blockIdx.x;
    int tid = threadIdx.x;
    int w = tid >> 5, lane = tid & 31;
    float acc = 0.0f;
    int f0 = w * 64;
#pragma unroll 8
    for (int f = f0; f < f0 + 64; ++f)
        acc += g_hsum[f * 32 + lane] * Wfc[(size_t)f * 256 + j];
    redsm[w][lane] = acc;
    __syncthreads();
    if (w == 0) {
        float s = 0.0f;
#pragma unroll
        for (int q = 0; q < 8; ++q) s += redsm[q][lane];
        float invlen = 1.0f / (float)lengths[lane];
        g_fc[j * 32 + lane] = fmaxf(s * invlen + bfc[j], 0.0f);
    }
}

// ---------------- kernel 4b: logits ----------------
__global__ void k4b_out(const float* __restrict__ Wout, const float* __restrict__ bout,
                        float* __restrict__ out) {
    int t = threadIdx.x;
    int b = t >> 1, lab = t & 1;
    float s = bout[lab];
#pragma unroll 8
    for (int j = 0; j < 256; ++j)
        s += g_fc[j * 32 + b] * Wout[j * 2 + lab];
    out[b * 2 + lab] = s;
}

// ---------------- launch ----------------
extern "C" void kernel_launch(void* const* d_in, const int* in_sizes, int n_in,
                              void* d_out, int out_size) {
    const float* emb  = (const float*)d_in[0];
    const float* Win  = (const float*)d_in[1];
    const float* bin  = (const float*)d_in[2];
    const float* Wihf = (const float*)d_in[3];
    const float* Whhf = (const float*)d_in[4];
    const float* blf  = (const float*)d_in[5];
    const float* Wihb = (const float*)d_in[6];
    const float* Whhb = (const float*)d_in[7];
    const float* blb  = (const float*)d_in[8];
    const float* Wfc  = (const float*)d_in[9];
    const float* bfc  = (const float*)d_in[10];
    const float* Wout = (const float*)d_in[11];
    const float* bout = (const float*)d_in[12];
    const int*   x    = (const int*)d_in[13];
    const int*   mask = (const int*)d_in[14];
    const int*   len  = (const int*)d_in[15];
    float* out = (float*)d_out;

    k1_embed<<<dim3(256, 4), 256>>>(emb, Win, bin, x);
    k2w_conv<<<2048, 256>>>(Wihf, Wihb);
    k2_hmma<<<dim3(128, 16), 256>>>(blf, blb);
    k3_lstm<<<128, 256>>>(Whhf, Whhb, mask);
    k4a_fc<<<256, 256>>>(Wfc, bfc, len);
    k4b_out<<<1, 64>>>(Wout, bout, out);
}

// round 16
// speedup vs baseline: 1.2262x; 1.0855x over previous
#include <cuda_runtime.h>
#include <cuda_bf16.h>
#include <cstdint>

#define B_    32
#define T_    512
#define H_    256
#define WDIM_ 300

typedef unsigned long long u64;

// ---------------- scratch (device globals; no allocation allowed) ----------------
__device__ __align__(16) __nv_bfloat16 g_zhi[16384 * 256];       // z split hi  [r][k]
__device__ __align__(16) __nv_bfloat16 g_zlo[16384 * 256];       // z split lo  [r][k]
__device__ __align__(16) __nv_bfloat16 g_wt[2][2][1024][256];    // [dir][part][c][k]
__device__ __align__(16) float g_gates[2 * 512 * 1024 * 32];     // [dir][t][col][b] 128 MB
__device__ __align__(16) float g_h[2][2][256 * 32];              // [buf][dir][k][b]
__device__ __align__(16) float g_hsum[512 * 32];                 // [feat][b]
__device__ __align__(16) float g_fc[256 * 32];                   // [j][b]
__device__ unsigned g_arrive[2];
__device__ unsigned g_gen[2];
__device__ __align__(128) unsigned g_flags[2][64];               // monotonic publish counters

// ---------------- f32x2 helpers (exact fp32 semantics; used in k1) ----------------
__device__ __forceinline__ u64 pk(float lo, float hi) {
    u64 r; asm("mov.b64 %0, {%1, %2};" : "=l"(r) : "f"(lo), "f"(hi)); return r;
}
__device__ __forceinline__ u64 dupf(float v) {
    u64 r; asm("mov.b64 %0, {%1, %1};" : "=l"(r) : "f"(v)); return r;
}
__device__ __forceinline__ void fma2(u64& d, u64 a, u64 b) {
    asm("fma.rn.f32x2 %0, %1, %2, %0;" : "+l"(d) : "l"(a), "l"(b));
}
__device__ __forceinline__ float2 upk(u64 v) {
    float2 f; asm("mov.b64 {%0, %1}, %2;" : "=f"(f.x), "=f"(f.y) : "l"(v)); return f;
}

__device__ __forceinline__ float sigf(float x) { return 1.0f / (1.0f + __expf(-x)); }

__device__ __forceinline__ unsigned ldacq(const unsigned* p) {
    unsigned v;
    asm volatile("ld.acquire.gpu.global.u32 %0, [%1];" : "=r"(v) : "l"(p) : "memory");
    return v;
}
__device__ __forceinline__ void red_release_add1(unsigned* p) {
    asm volatile("red.release.gpu.global.add.u32 [%0], 1;" :: "l"(p) : "memory");
}

// warp-level bf16 MMA (sm_80+ baseline; works on compute_103)
__device__ __forceinline__ void mma16816(float* c, const unsigned* a, unsigned b0, unsigned b1) {
    asm volatile(
        "mma.sync.aligned.m16n8k16.row.col.f32.bf16.bf16.f32 "
        "{%0,%1,%2,%3}, {%4,%5,%6,%7}, {%8,%9}, {%0,%1,%2,%3};"
        : "+f"(c[0]), "+f"(c[1]), "+f"(c[2]), "+f"(c[3])
        : "r"(a[0]), "r"(a[1]), "r"(a[2]), "r"(a[3]), "r"(b0), "r"(b1));
}

// cp.async 16B (sm_80+ baseline)
__device__ __forceinline__ void cpa16(const void* sptr, const void* gptr) {
    unsigned sa = (unsigned)__cvta_generic_to_shared(sptr);
    asm volatile("cp.async.cg.shared.global [%0], [%1], 16;" :: "r"(sa), "l"(gptr));
}

__device__ __forceinline__ void bf16split(float v, __nv_bfloat16& h, __nv_bfloat16& l) {
    h = __float2bfloat16(v);
    l = __float2bfloat16(v - __bfloat162float(h));
}

// Sense-reversing barrier among the 64 CTAs of one direction (used ONCE at start of k3).
__device__ __forceinline__ void dir_barrier(int dir, unsigned ncta) {
    __syncthreads();
    if (threadIdx.x == 0) {
        volatile unsigned* gen = &g_gen[dir];
        unsigned old = *gen;
        __threadfence();
        unsigned a = atomicAdd(&g_arrive[dir], 1u);
        if (a == ncta - 1u) {
            g_arrive[dir] = 0u;
            __threadfence();
            atomicExch((unsigned*)&g_gen[dir], old + 1u);
        } else {
            while (*gen == old) { }
        }
        __threadfence();
    }
    __syncthreads();
}

// ---------------- kernel 1: z = relu(emb[x] @ W_in + b_in) -> bf16 hi/lo ----------------
__global__ void k1_embed(const float* __restrict__ emb, const float* __restrict__ Win,
                         const float* __restrict__ bin, const int* __restrict__ x) {
    __shared__ float As[12][68];
    __shared__ float Bs[12][68];
    __shared__ int   xid[64];
    int tid = threadIdx.x;
    int r0 = blockIdx.x * 64;
    int c0 = blockIdx.y * 64;
    if (tid < 64) {
        int r = r0 + tid;
        int b = r & 31, t = r >> 5;
        xid[tid] = x[b * T_ + t];
    }
    __syncthreads();
    int tx = tid & 15, ty = tid >> 4;
    u64 acc2[2][4];
#pragma unroll
    for (int p = 0; p < 2; ++p)
#pragma unroll
        for (int j = 0; j < 4; ++j) acc2[p][j] = 0ULL;

    int ar = tid >> 2, ag = (tid & 3) * 3;
    int bc = tid & 63, bg = (tid >> 6) * 3;

    for (int k0 = 0; k0 < WDIM_; k0 += 12) {
        const float* ep = emb + (size_t)xid[ar] * WDIM_ + k0 + ag;
        As[ag + 0][ar] = ep[0];
        As[ag + 1][ar] = ep[1];
        As[ag + 2][ar] = ep[2];
#pragma unroll
        for (int j = 0; j < 3; ++j)
            Bs[bg + j][bc] = Win[(size_t)(k0 + bg + j) * H_ + c0 + bc];
        __syncthreads();
#pragma unroll
        for (int kk = 0; kk < 12; ++kk) {
            float4 a  = *(const float4*)&As[kk][ty * 4];
            float4 bv = *(const float4*)&Bs[kk][tx * 4];
            u64 ap0 = pk(a.x, a.y), ap1 = pk(a.z, a.w);
            u64 bd0 = dupf(bv.x), bd1 = dupf(bv.y), bd2 = dupf(bv.z), bd3 = dupf(bv.w);
            fma2(acc2[0][0], ap0, bd0); fma2(acc2[0][1], ap0, bd1);
            fma2(acc2[0][2], ap0, bd2); fma2(acc2[0][3], ap0, bd3);
            fma2(acc2[1][0], ap1, bd0); fma2(acc2[1][1], ap1, bd1);
            fma2(acc2[1][2], ap1, bd2); fma2(acc2[1][3], ap1, bd3);
        }
        __syncthreads();
    }
    float bj[4];
#pragma unroll
    for (int j = 0; j < 4; ++j) bj[j] = bin[c0 + tx * 4 + j];
#pragma unroll
    for (int p = 0; p < 2; ++p) {
        float2 uu[4];
#pragma unroll
        for (int j = 0; j < 4; ++j) uu[j] = upk(acc2[p][j]);
        float vr[2][4];
#pragma unroll
        for (int j = 0; j < 4; ++j) {
            vr[0][j] = fmaxf(uu[j].x + bj[j], 0.0f);
            vr[1][j] = fmaxf(uu[j].y + bj[j], 0.0f);
        }
#pragma unroll
        for (int q = 0; q < 2; ++q) {
            int r = r0 + ty * 4 + p * 2 + q;
            size_t base = (size_t)r * 256 + c0 + tx * 4;
            __nv_bfloat16 h[4], l[4];
#pragma unroll
            for (int j = 0; j < 4; ++j) bf16split(vr[q][j], h[j], l[j]);
            *(__nv_bfloat162*)&g_zhi[base]     = __nv_bfloat162{h[0], h[1]};
            *(__nv_bfloat162*)&g_zhi[base + 2] = __nv_bfloat162{h[2], h[3]};
            *(__nv_bfloat162*)&g_zlo[base]     = __nv_bfloat162{l[0], l[1]};
            *(__nv_bfloat162*)&g_zlo[base + 2] = __nv_bfloat162{l[2], l[3]};
        }
    }
}

// ---------------- kernel 2w: split/transpose Wih -> g_wt[dir][part][c][k] ----------------
__global__ void k2w_conv(const float* __restrict__ Wf, const float* __restrict__ Wb) {
    int gid = blockIdx.x * 256 + threadIdx.x;     // 2*1024*256 total
    int k = gid & 255;
    int c = (gid >> 8) & 1023;
    int dir = gid >> 18;
    float w = (dir ? Wb : Wf)[(size_t)k * 1024 + c];
    __nv_bfloat16 hi, lo;
    bf16split(w, hi, lo);
    g_wt[dir][0][c][k] = hi;
    g_wt[dir][1][c][k] = lo;
}

// ---------------- kernel 2: pipelined HMMA bf16-split GEMM: gates = z @ Wih + bl ----------
// CTA tile 128x128, K-chunk 32, two cp.async stages, one barrier per chunk.
#define BST 40   // smem row stride in bf16 elements
__global__ void __launch_bounds__(256) k2_hmma(const float* __restrict__ blf,
                                               const float* __restrict__ blb) {
    __shared__ __align__(16) __nv_bfloat16 sm[2][2][128 * BST];  // 40960 B
    float* Sc = (float*)sm;                                      // epilogue alias

    int tid = threadIdx.x;
    int wid = tid >> 5, lane = tid & 31;
    int g = lane >> 2, tg = lane & 3;
    int wm = wid & 3, wn = wid >> 2;
    int bx = blockIdx.x, by = blockIdx.y;
    int dir = by >> 3;
    int c0  = (by & 7) * 128;
    int r0  = bx * 128;
    int row2 = tid >> 1, half = tid & 1;

    float c[2][8][4];
#pragma unroll
    for (int mi = 0; mi < 2; ++mi)
#pragma unroll
        for (int ni = 0; ni < 8; ++ni)
#pragma unroll
            for (int q = 0; q < 4; ++q) c[mi][ni][q] = 0.0f;

    int m0 = wm * 32;
    int n0 = wn * 64;

    auto prefetch = [&](int it) {
        int seg = it >> 3, chunk = it & 7;
        const __nv_bfloat16* Ag = (seg < 2) ? g_zhi : g_zlo;
        const __nv_bfloat16* Bg = &g_wt[dir][(seg == 1) ? 1 : 0][c0][0];
        int st = it & 1;
        const __nv_bfloat16* as = Ag + (size_t)(r0 + row2) * 256 + chunk * 32 + half * 16;
        const __nv_bfloat16* bs = Bg + (size_t)row2 * 256 + chunk * 32 + half * 16;
        __nv_bfloat16* ad = &sm[st][0][row2 * BST + half * 16];
        __nv_bfloat16* bd = &sm[st][1][row2 * BST + half * 16];
        cpa16(ad, as); cpa16(ad + 8, as + 8);
        cpa16(bd, bs); cpa16(bd + 8, bs + 8);
        asm volatile("cp.async.commit_group;" ::: "memory");
    };

    prefetch(0);
    for (int it = 0; it < 24; ++it) {
        asm volatile("cp.async.wait_group 0;" ::: "memory");
        __syncthreads();
        if (it < 23) prefetch(it + 1);
        int st = it & 1;
        const __nv_bfloat16* As = sm[st][0];
        const __nv_bfloat16* Bs = sm[st][1];
#pragma unroll
        for (int ks = 0; ks < 2; ++ks) {
            int k1 = ks * 16;
            unsigned a[2][4];
#pragma unroll
            for (int mi = 0; mi < 2; ++mi) {
                const __nv_bfloat16* ab = As + (m0 + mi * 16 + g) * BST + k1 + tg * 2;
                a[mi][0] = *(const unsigned*)ab;
                a[mi][1] = *(const unsigned*)(ab + 8 * BST);
                a[mi][2] = *(const unsigned*)(ab + 8);
                a[mi][3] = *(const unsigned*)(ab + 8 * BST + 8);
            }
#pragma unroll
            for (int ni = 0; ni < 8; ++ni) {
                const __nv_bfloat16* bb = Bs + (n0 + ni * 8 + g) * BST + k1 + tg * 2;
                unsigned b0 = *(const unsigned*)bb;
                unsigned b1 = *(const unsigned*)(bb + 8);
                mma16816(c[0][ni], a[0], b0, b1);
                mma16816(c[1][ni], a[1], b0, b1);
            }
        }
    }
    __syncthreads();   // all MMAs done before Sc (alias) writes

    const float* bl = dir ? blb : blf;
    int t = bx * 4 + wm;
    float* myS = Sc + wid * (8 * 33);
    size_t gbase = (size_t)(dir * 512 + t) * (1024 * 32);
#pragma unroll
    for (int ni = 0; ni < 8; ++ni) {
#pragma unroll
        for (int mi = 0; mi < 2; ++mi)
#pragma unroll
            for (int q = 0; q < 4; ++q) {
                int col_local = tg * 2 + (q & 1);
                int row_local = mi * 16 + g + ((q >> 1) ? 8 : 0);
                myS[col_local * 33 + row_local] = c[mi][ni][q];
            }
        __syncwarp();
#pragma unroll
        for (int col = 0; col < 8; ++col) {
            int cg = c0 + n0 + ni * 8 + col;
            float v = myS[col * 33 + lane] + __ldg(&bl[cg]);
            g_gates[gbase + (size_t)cg * 32 + lane] = v;
        }
        __syncwarp();
    }
}

// ---------------- kernel 3: persistent BiLSTM recurrence ----------------
// R12 skeleton with red UN-ALIASED from As (dynamic smem 50304 B):
//  - syncB -> __syncwarp (As is fully warp-local: copy writes + frag reads
//    both touch only the warp's own k columns)
//  - sync1 removed (no alias hazard; cross-iter ordering via syncA)
// Per step: 2 block syncs (syncA, sync2) + 1 syncwarp.
#define AST   522
#define AST_W 261
#define K3_SMEM (32 * AST * 2 + 8 * 528 * 4)   // 33408 + 16896 = 50304
__global__ void __launch_bounds__(256, 1)
k3_lstm(const float* __restrict__ Whhf, const float* __restrict__ Whhb,
        const int* __restrict__ mask) {
    extern __shared__ __align__(16) unsigned char smdyn[];
    __nv_bfloat16* As = (__nv_bfloat16*)smdyn;             // 33408 B, warp-local
    unsigned* Asw = (unsigned*)smdyn;
    float* red = (float*)(smdyn + 32 * AST * 2);           // 16896 B, separate

    int cta   = blockIdx.x;
    int dir   = cta >> 6;
    int slice = cta & 63;
    int u0    = slice << 2;
    const float* Whh = dir ? Whhb : Whhf;
    int tid  = threadIdx.x;
    int warp = tid >> 5, lane = tid & 31;
    int g = lane >> 2, tg = lane & 3;
    int kbase = warp << 5;

    unsigned bhi[2][2][2], blo[2][2][2];
#pragma unroll
    for (int kt = 0; kt < 2; ++kt)
#pragma unroll
        for (int nt = 0; nt < 2; ++nt)
#pragma unroll
            for (int r = 0; r < 2; ++r) {
                int n  = nt * 8 + g;
                int gc = (n >> 2) * 256 + u0 + (n & 3);
                int k  = kbase + kt * 16 + tg * 2 + r * 8;
                float w0 = Whh[(size_t)k * 1024 + gc];
                float w1 = Whh[(size_t)(k + 1) * 1024 + gc];
                __nv_bfloat16 h0, l0, h1, l1;
                bf16split(w0, h0, l0);
                bf16split(w1, h1, l1);
                __nv_bfloat162 ph{h0, h1}, pl{l0, l1};
                bhi[kt][nt][r] = *(unsigned*)&ph;
                blo[kt][nt][r] = *(unsigned*)&pl;
            }

    int u = tid >> 5;        // valid for tid < 128
    int b = tid & 31;
    float c_reg = 0.0f, h_reg = 0.0f, hsum_reg = 0.0f;
    if (tid < 128) g_h[0][dir][(u0 + u) * 32 + b] = 0.0f;

    unsigned base = 0;
    const unsigned* myflag = 0;
    if (tid >= 192) {
        myflag = &g_flags[dir][tid - 192];
        base = ldacq(myflag);
    }
    dir_barrier(dir, 64);    // zeros + base reads complete before any publish

    unsigned* pubflag = &g_flags[dir][slice];
    int kp  = lane >> 3;
    int b0c = (lane & 7) * 4;

    for (int t = 0; t < T_; ++t) {
        int cur = t & 1, nxt = cur ^ 1;
        int tt = dir ? (T_ - 1 - t) : t;

        // prefetch gate preactivations + mask (in flight during spin)
        float gpre0 = 0.f, gpre1 = 0.f, gpre2 = 0.f, gpre3 = 0.f, mval = 0.f;
        if (tid < 128) {
            const float* gp = g_gates + (size_t)(dir * 512 + tt) * (1024 * 32);
            gpre0 = gp[(0 * 256 + u0 + u) * 32 + b];
            gpre1 = gp[(1 * 256 + u0 + u) * 32 + b];
            gpre2 = gp[(2 * 256 + u0 + u) * 32 + b];
            gpre3 = gp[(3 * 256 + u0 + u) * 32 + b];
            mval  = (float)mask[b * T_ + tt];
        }

        // wait: all 64 producers published h(t)
        if (tid >= 192) {
            unsigned need = 128u * (unsigned)t;
            while (ldacq(myflag) - base < need) { }
        }
        __syncthreads();   // syncA: h(t) visible + red reads (prev iter) done

        // copy + convert: warp fills its OWN k columns of As (warp-local)
#pragma unroll
        for (int p = 0; p < 4; ++p) {
            int k = kbase + p * 8 + kp * 2;
            float4 ha = __ldcg((const float4*)&g_h[cur][dir][k * 32 + b0c]);
            float4 hb = __ldcg((const float4*)&g_h[cur][dir][(k + 1) * 32 + b0c]);
            float va[4] = {ha.x, ha.y, ha.z, ha.w};
            float vb[4] = {hb.x, hb.y, hb.z, hb.w};
#pragma unroll
            for (int j = 0; j < 4; ++j) {
                unsigned ba = __float_as_uint(va[j]);
                unsigned bb = __float_as_uint(vb[j]);
                unsigned hiw = __byte_perm(ba, bb, 0x7632);
                float ra = va[j] - __uint_as_float(ba & 0xFFFF0000u);
                float rb = vb[j] - __uint_as_float(bb & 0xFFFF0000u);
                unsigned low;
                asm("cvt.rn.bf16x2.f32 %0, %1, %2;" : "=r"(low) : "f"(rb), "f"(ra));
                int row = b0c + j;
                Asw[row * AST_W + (k >> 1)]       = hiw;
                Asw[row * AST_W + 128 + (k >> 1)] = low;
            }
        }
        __syncwarp();      // As is warp-local: warp sync suffices

        // 3-term bf16 split MMA over this warp's k slice
        float c[2][2][4];
#pragma unroll
        for (int mi = 0; mi < 2; ++mi)
#pragma unroll
            for (int ni = 0; ni < 2; ++ni)
#pragma unroll
                for (int q = 0; q < 4; ++q) c[mi][ni][q] = 0.0f;

        unsigned afr[2][2][4];
#pragma unroll
        for (int kt = 0; kt < 2; ++kt)
#pragma unroll
            for (int mi = 0; mi < 2; ++mi) {
                const __nv_bfloat16* ab = As + (mi * 16 + g) * AST + kbase + kt * 16 + tg * 2;
                afr[kt][mi][0] = *(const unsigned*)ab;
                afr[kt][mi][1] = *(const unsigned*)(ab + 8 * AST);
                afr[kt][mi][2] = *(const unsigned*)(ab + 8);
                afr[kt][mi][3] = *(const unsigned*)(ab + 8 * AST + 8);
            }
#pragma unroll
        for (int kt = 0; kt < 2; ++kt)
#pragma unroll
            for (int mi = 0; mi < 2; ++mi)
#pragma unroll
                for (int ni = 0; ni < 2; ++ni) {
                    mma16816(c[mi][ni], afr[kt][mi], bhi[kt][ni][0], bhi[kt][ni][1]);  // hi*Whi
                    mma16816(c[mi][ni], afr[kt][mi], blo[kt][ni][0], blo[kt][ni][1]);  // hi*Wlo
                }
#pragma unroll
        for (int kt = 0; kt < 2; ++kt)
#pragma unroll
            for (int mi = 0; mi < 2; ++mi) {
                const __nv_bfloat16* ab = As + (mi * 16 + g) * AST + 256 + kbase + kt * 16 + tg * 2;
                afr[kt][mi][0] = *(const unsigned*)ab;
                afr[kt][mi][1] = *(const unsigned*)(ab + 8 * AST);
                afr[kt][mi][2] = *(const unsigned*)(ab + 8);
                afr[kt][mi][3] = *(const unsigned*)(ab + 8 * AST + 8);
            }
#pragma unroll
        for (int kt = 0; kt < 2; ++kt)
#pragma unroll
            for (int mi = 0; mi < 2; ++mi)
#pragma unroll
                for (int ni = 0; ni < 2; ++ni)
                    mma16816(c[mi][ni], afr[kt][mi], bhi[kt][ni][0], bhi[kt][ni][1]);  // lo*Whi

        // red is a separate buffer: write directly (no alias barrier needed)
#pragma unroll
        for (int mi = 0; mi < 2; ++mi)
#pragma unroll
            for (int ni = 0; ni < 2; ++ni)
#pragma unroll
                for (int q = 0; q < 4; ++q) {
                    int row = mi * 16 + g + ((q >> 1) ? 8 : 0);
                    int col = ni * 8 + tg * 2 + (q & 1);
                    red[warp * 528 + col * 33 + row] = c[mi][ni][q];
                }
        __syncthreads();   // sync2: all warps' red complete before gate reads

        if (tid < 128) {
            float z0 = gpre0, z1 = gpre1, z2 = gpre2, z3 = gpre3;
#pragma unroll
            for (int w = 0; w < 8; ++w) {
                const float* rp = red + w * 528 + b;
                z0 += rp[(0 + u) * 33];
                z1 += rp[(4 + u) * 33];
                z2 += rp[(8 + u) * 33];
                z3 += rp[(12 + u) * 33];
            }
            float ig = sigf(z0), fg = sigf(z1);
            float gg = tanhf(z2), og = sigf(z3);
            float cn = fg * c_reg + ig * gg;
            float hn = og * tanhf(cn);
            c_reg = mval * cn + (1.0f - mval) * c_reg;
            h_reg = mval * hn + (1.0f - mval) * h_reg;
            hsum_reg += mval * h_reg;
            g_h[nxt][dir][(u0 + u) * 32 + b] = h_reg;
            red_release_add1(pubflag);   // release orders this thread's h store
        }
    }
    if (tid < 128) g_hsum[((dir << 8) + u0 + u) * 32 + b] = hsum_reg;
}

// ---------------- kernel 4a: fc_hidden[j][b], one CTA per j ----------------
__global__ void k4a_fc(const float* __restrict__ Wfc, const float* __restrict__ bfc,
                       const int* __restrict__ lengths) {
    __shared__ float redsm[8][32];
    int j = blockIdx.x;
    int tid = threadIdx.x;
    int w = tid >> 5, lane = tid & 31;
    float acc = 0.0f;
    int f0 = w * 64;
#pragma unroll 8
    for (int f = f0; f < f0 + 64; ++f)
        acc += g_hsum[f * 32 + lane] * Wfc[(size_t)f * 256 + j];
    redsm[w][lane] = acc;
    __syncthreads();
    if (w == 0) {
        float s = 0.0f;
#pragma unroll
        for (int q = 0; q < 8; ++q) s += redsm[q][lane];
        float invlen = 1.0f / (float)lengths[lane];
        g_fc[j * 32 + lane] = fmaxf(s * invlen + bfc[j], 0.0f);
    }
}

// ---------------- kernel 4b: logits ----------------
__global__ void k4b_out(const float* __restrict__ Wout, const float* __restrict__ bout,
                        float* __restrict__ out) {
    int t = threadIdx.x;
    int b = t >> 1, lab = t & 1;
    float s = bout[lab];
#pragma unroll 8
    for (int j = 0; j < 256; ++j)
        s += g_fc[j * 32 + b] * Wout[j * 2 + lab];
    out[b * 2 + lab] = s;
}

// ---------------- launch ----------------
extern "C" void kernel_launch(void* const* d_in, const int* in_sizes, int n_in,
                              void* d_out, int out_size) {
    const float* emb  = (const float*)d_in[0];
    const float* Win  = (const float*)d_in[1];
    const float* bin  = (const float*)d_in[2];
    const float* Wihf = (const float*)d_in[3];
    const float* Whhf = (const float*)d_in[4];
    const float* blf  = (const float*)d_in[5];
    const float* Wihb = (const float*)d_in[6];
    const float* Whhb = (const float*)d_in[7];
    const float* blb  = (const float*)d_in[8];
    const float* Wfc  = (const float*)d_in[9];
    const float* bfc  = (const float*)d_in[10];
    const float* Wout = (const float*)d_in[11];
    const float* bout = (const float*)d_in[12];
    const int*   x    = (const int*)d_in[13];
    const int*   mask = (const int*)d_in[14];
    const int*   len  = (const int*)d_in[15];
    float* out = (float*)d_out;

    // opt-in to >48KB dynamic smem for k3 (config call; not a stream op)
    static bool attr_done = false;
    if (!attr_done) {
        cudaFuncSetAttribute(k3_lstm, cudaFuncAttributeMaxDynamicSharedMemorySize, K3_SMEM);
        attr_done = true;
    }

    k1_embed<<<dim3(256, 4), 256>>>(emb, Win, bin, x);
    k2w_conv<<<2048, 256>>>(Wihf, Wihb);
    k2_hmma<<<dim3(128, 16), 256>>>(blf, blb);
    k3_lstm<<<128, 256, K3_SMEM>>>(Whhf, Whhb, mask);
    k4a_fc<<<256, 256>>>(Wfc, bfc, len);
    k4b_out<<<1, 64>>>(Wout, bout, out);
}